// round 14
// baseline (speedup 1.0000x reference)
#include <cuda_runtime.h>
#include <cstdint>

#define BB 512
#define TT 4096
#define SS 64
#define MM 125
#define CHUNK 512                 // time-steps per producer/consumer chunk
#define NCHUNK (TT / CHUNK)       // 8

// packed f32x2 FMA — only reachable via PTX (ptxas never auto-fuses)
__device__ __forceinline__ void ffma2(float2& d, float2 a, float2 b, float2 c) {
    asm("fma.rn.f32x2 %0, %1, %2, %3;"
        : "=l"(*(unsigned long long*)&d)
        : "l"(*(unsigned long long*)&a),
          "l"(*(unsigned long long*)&b),
          "l"(*(unsigned long long*)&c));
}

// chunk rendezvous: scan warps 2p, 2p+1 + decoder warp 8+p (96 threads)
__device__ __forceinline__ void pair_bar(int p) {
    asm volatile("bar.sync %0, 96;" :: "r"(p + 1) : "memory");
}

// One matvec + emission multiply: u = E .* (alpha @ A), alpha read from rb.
__device__ __forceinline__ void matvec_step(
    const float* __restrict__ rb, float2 e,
    const float2* __restrict__ aA, const float2* __restrict__ aB,
    float& u0, float& u1)
{
    const float4* ap = (const float4*)rb;
    float2 A0 = {0.f,0.f}, A1 = {0.f,0.f}, B0 = {0.f,0.f}, B1 = {0.f,0.f};
#pragma unroll
    for (int q = 0; q < 16; q++) {
        float4 al = ap[q];                       // alpha[4q..4q+3] (broadcast LDS.128)
        float2 lo = make_float2(al.x, al.y);
        float2 hi = make_float2(al.z, al.w);
        ffma2(A0, lo, aA[2 * q],     A0);
        ffma2(A1, hi, aA[2 * q + 1], A1);
        ffma2(B0, lo, aB[2 * q],     B0);
        ffma2(B1, hi, aB[2 * q + 1], B1);
    }
    float r0 = (A0.x + A0.y) + (A1.x + A1.y);
    float r1 = (B0.x + B0.y) + (B1.x + B1.y);
    u0 = e.x * r0;
    u1 = e.y * r1;
}

// 8 straight-line steps; static buffer parity; renorm (1 shfl) only at step 7.
template<bool INIT>
__device__ __forceinline__ void block8(
    const unsigned char* __restrict__ obs8,
    const float2* __restrict__ sB2,
    float* __restrict__ buf0, float* __restrict__ buf1,
    const float2* __restrict__ aA, const float2* __restrict__ aB,
    float& u0, float& u1, int& esum, int lane, float i0, float i1)
{
    uint2 ow = *(const uint2*)obs8;              // 8 obs bytes in 2 registers

#pragma unroll
    for (int i = 0; i < 8; i++) {
        unsigned word = (i < 4) ? ow.x : ow.y;
        int ob = (word >> ((i & 3) * 8)) & 0xff;
        float2 e = sB2[ob * 32 + lane];          // LDS.64, issued ahead of FMAs

        if (INIT && i == 0) {
            u0 = e.x * i0;                       // t=0: u = E0 * I (unnormalized)
            u1 = e.y * i1;
        } else {
            const float* rb = (i & 1) ? buf0 : buf1;
            matvec_step(rb, e, aA, aB, u0, u1);
        }

        if (i == 7) {
            // exact power-of-two rescale from lane 0's exponent; log deferred
            float w0 = __shfl_sync(0xffffffffu, u0, 0);
            int ex = (int)((__float_as_uint(w0) >> 23) & 0xff) - 127;
            esum += ex;
            float sc = __uint_as_float((unsigned)(127 - ex) << 23);   // 2^-ex
            u0 *= sc;
            u1 *= sc;
        }

        float* wb = (i & 1) ? buf1 : buf0;
        wb[lane]      = u0;
        wb[lane + 32] = u1;
        // convergent warp: same-warp STS->LDS is HW-ordered; block only the
        // compiler from reordering smem accesses across steps.
        asm volatile("" ::: "memory");
    }
}

// ---------------------------------------------------------------------------
// Fused kernel, 384 threads/CTA, 64 CTAs (8 chains per CTA):
//   warps 0-7 : scan warps, one full chain each (no cross-warp sync in-step).
//               SMSP k hosts scan warps k and k+4 -> two independent chains
//               interleave and hide each other's latency.
//   warps 8-11: decoder warp p feeds chains 2p and 2p+1.
// ---------------------------------------------------------------------------
__global__ void __launch_bounds__(384, 1) fused_hmm_kernel(
    const float* __restrict__ x,
    const float* __restrict__ Ivec,
    const float* __restrict__ A,
    const float* __restrict__ Bm,
    float* __restrict__ out)
{
    __shared__ float2 sB2[MM * 32];                          // 32000 B
    __shared__ float sAlpha[8][2][SS];                       //  4096 B
    __shared__ __align__(16) unsigned char sObs[8][2][CHUNK];//  8192 B

    const int tid  = threadIdx.x;
    const int w    = tid >> 5;          // 0..11
    const int lane = tid & 31;

    // stage Bm into shared as (Bm[m][l], Bm[m][l+32]) pairs
    for (int i = tid; i < MM * 32; i += 384) {
        int m = i >> 5, l = i & 31;
        sB2[i] = make_float2(Bm[m * SS + l], Bm[m * SS + 32 + l]);
    }
    __syncthreads();

    if (w >= 8) {
        // ---------- decoder warp p: chains 2p and 2p+1 ----------
        const int p  = w - 8;
        const int b0 = blockIdx.x * 8 + 2 * p;
        for (int c = 0; c < NCHUNK; c++) {
            const unsigned jbase = c * (CHUNK * MM);
            const unsigned rbase = c * CHUNK;
#pragma unroll
            for (int half = 0; half < 2; half++) {
                unsigned char* dst = sObs[2 * p + half][c & 1];
                const float4* base = (const float4*)(x + (size_t)(b0 + half) * TT * MM)
                                     + c * (CHUNK * MM / 4);   // 16000 float4/chunk
                for (int i = lane; i < CHUNK * MM / 4; i += 32) {
                    float4 v = __ldcs(base + i);
                    unsigned j = jbase + 4u * i;
                    if (v.x > 0.5f) { unsigned r = j / 125u;        dst[r - rbase] = (unsigned char)(j - r * 125u); }
                    if (v.y > 0.5f) { unsigned r = (j + 1) / 125u;  dst[r - rbase] = (unsigned char)(j + 1 - r * 125u); }
                    if (v.z > 0.5f) { unsigned r = (j + 2) / 125u;  dst[r - rbase] = (unsigned char)(j + 2 - r * 125u); }
                    if (v.w > 0.5f) { unsigned r = (j + 3) / 125u;  dst[r - rbase] = (unsigned char)(j + 3 - r * 125u); }
                }
            }
            pair_bar(p);   // both chains' chunk c ready; scanners freed other buffer
        }
    } else {
        // ---------- scan warp: full chain w ----------
        const int p = w >> 1;           // rendezvous pair id
        const int b = blockIdx.x * 8 + w;

        // A column k-pairs in registers (loop-invariant):
        float2 aA[32], aB[32];
#pragma unroll
        for (int kp = 0; kp < 32; kp++) {
            aA[kp].x = A[(2 * kp)     * SS + lane];
            aA[kp].y = A[(2 * kp + 1) * SS + lane];
            aB[kp].x = A[(2 * kp)     * SS + lane + 32];
            aB[kp].y = A[(2 * kp + 1) * SS + lane + 32];
        }
        const float i0 = Ivec[lane];
        const float i1 = Ivec[lane + 32];

        float* buf0 = sAlpha[w][0];
        float* buf1 = sAlpha[w][1];
        float u0, u1;
        int esum = 0;

        // ---- chunk 0 ----
        pair_bar(p);
        {
            const unsigned char* ob = sObs[w][0];
            block8<true>(ob, sB2, buf0, buf1, aA, aB, u0, u1, esum, lane, i0, i1);
            for (int blk = 1; blk < CHUNK / 8; blk++)
                block8<false>(ob + blk * 8, sB2, buf0, buf1, aA, aB, u0, u1, esum, lane, i0, i1);
        }
        // ---- chunks 1..7 ----
        for (int c = 1; c < NCHUNK; c++) {
            pair_bar(p);
            const unsigned char* ob = sObs[w][c & 1];
            for (int blk = 0; blk < CHUNK / 8; blk++)
                block8<false>(ob + blk * 8, sB2, buf0, buf1, aA, aB, u0, u1, esum, lane, i0, i1);
        }

        // single exact reduction + log at the end:
        float s = u0 + u1;
#pragma unroll
        for (int o = 16; o; o >>= 1) s += __shfl_xor_sync(0xffffffffu, s, o);
        if (lane == 0) out[b] = (float)esum * 0.6931471805599453f + logf(s);
    }
}

extern "C" void kernel_launch(void* const* d_in, const int* in_sizes, int n_in,
                              void* d_out, int out_size) {
    const float* x  = (const float*)d_in[0];   // [512, 4096, 125]
    const float* I  = (const float*)d_in[1];   // [1, 64]
    const float* A  = (const float*)d_in[2];   // [64, 64]
    const float* Bm = (const float*)d_in[3];   // [125, 64]
    float* out = (float*)d_out;                // [512, 1]

    fused_hmm_kernel<<<BB / 8, 384>>>(x, I, A, Bm, out);
}

// round 16
// speedup vs baseline: 1.9466x; 1.9466x over previous
#include <cuda_runtime.h>
#include <cuda_fp16.h>
#include <cstdint>

#define BB 512
#define TT 4096
#define SS 64
#define MM 125
#define CHUNK 512                 // time-steps per producer/consumer chunk
#define NCHUNK (TT / CHUNK)       // 8

// pair rendezvous: scanner warp p and decoder warp p+4, named barrier p+1
__device__ __forceinline__ void pair_bar(int p) {
    asm volatile("bar.sync %0, 64;" :: "r"(p + 1) : "memory");
}

__device__ __forceinline__ __half2 u2h(unsigned v) { return *(__half2*)&v; }
__device__ __forceinline__ unsigned h2u(__half2 v) { return *(unsigned*)&v; }

// 2^-ex as a dup half2 (ex pre-clamped to [-14,14])
__device__ __forceinline__ __half2 pow2_dup(int ex) {
    unsigned hb = (unsigned)(15 - ex) << 10;     // fp16 exponent field
    unsigned w  = hb | (hb << 16);
    return u2h(w);
}

// One scan step (fp16):
//   R = alpha_{t-1} @ A   (64 HFMA2, alpha as dup-half2 broadcast from smem)
//   u = e .* R .* s       (s = 2^-exA, lagged Z-centering scale)
//   store dup pairs; butterfly-reduce Z of stored u (fp32) -> next exA.
template<bool INIT>
__device__ __forceinline__ void hmm_step(
    int i, int ob,
    const unsigned* __restrict__ sBh,
    const unsigned* __restrict__ buf0, const unsigned* __restrict__ buf1,
    unsigned* __restrict__ wbuf0, unsigned* __restrict__ wbuf1,
    const __half2* __restrict__ aT,
    __half2& sdup, int& exA, int& esum, float& zout,
    int lane, float i0, float i1)
{
    __half2 e = u2h(sBh[ob * 32 + lane]);        // (Bm[ob][2l], Bm[ob][2l+1])
    __half2 u;

    if (INIT) {
        // t=0 in fp32: u = E0 * I, center on Z immediately
        float ux = __low2float(e)  * i0;
        float uy = __high2float(e) * i1;
        float z = ux + uy;
#pragma unroll
        for (int o = 16; o; o >>= 1) z += __shfl_xor_sync(0xffffffffu, z, o);
        int ex = (int)((__float_as_uint(z) >> 23) & 0xff) - 127;
        esum = ex;                                // applied at store below
        float sc = __uint_as_float((unsigned)(127 - ex) << 23);   // 2^-ex
        u = __floats2half2_rn(ux * sc, uy * sc);
    } else {
        const unsigned* rb = (i & 1) ? buf0 : buf1;
        const uint4* ap = (const uint4*)rb;
        __half2 a0 = __float2half2_rn(0.f), a1 = __float2half2_rn(0.f);
        __half2 a2 = __float2half2_rn(0.f), a3 = __float2half2_rn(0.f);
#pragma unroll
        for (int q = 0; q < 16; q++) {
            uint4 wv = ap[q];                     // dup(alpha_{4q..4q+3})
            a0 = __hfma2(u2h(wv.x), aT[4 * q    ], a0);
            a1 = __hfma2(u2h(wv.y), aT[4 * q + 1], a1);
            a2 = __hfma2(u2h(wv.z), aT[4 * q + 2], a2);
            a3 = __hfma2(u2h(wv.w), aT[4 * q + 3], a3);
        }
        __half2 R = __hadd2(__hadd2(a0, a1), __hadd2(a2, a3));
        u = __hmul2(__hmul2(e, R), sdup);         // apply lagged scale
        esum += exA;                              // account the applied power
    }

    // store duplicated pairs for next step's broadcast loads
    unsigned* wb = (i & 1) ? wbuf1 : wbuf0;
    wb[2 * lane]     = h2u(__half2half2(__low2half(u)));
    wb[2 * lane + 1] = h2u(__half2half2(__high2half(u)));
    asm volatile("" ::: "memory");               // convergent warp: HW-ordered

    // Z of stored alpha (fp32 butterfly); consumed next step -> latency hides
    float z = __low2float(u) + __high2float(u);
#pragma unroll
    for (int o = 16; o; o >>= 1) z += __shfl_xor_sync(0xffffffffu, z, o);
    int ex = (int)((__float_as_uint(z) >> 23) & 0xff) - 127;
    ex = ex < -14 ? -14 : (ex > 14 ? 14 : ex);
    exA = ex;
    sdup = pow2_dup(ex);
    zout = z;
}

// ---------------------------------------------------------------------------
// Fused kernel, 256 threads/CTA, 128 CTAs:
//   warps 0-3 : scan warps, one chain each (fp16 matvec)
//   warps 4-7 : decoder warps, stream + argmax-decode the partner chain
// ---------------------------------------------------------------------------
__global__ void __launch_bounds__(256, 1) fused_hmm_kernel(
    const float* __restrict__ x,
    const float* __restrict__ Ivec,
    const float* __restrict__ A,
    const float* __restrict__ Bm,
    float* __restrict__ out)
{
    __shared__ __align__(16) unsigned sBh[MM * 32];           // 16000 B, half2 e-pairs
    __shared__ __align__(16) unsigned sAh[4][2][SS];          //  2048 B, dup half2 alpha
    __shared__ __align__(16) unsigned char sObs[4][2][CHUNK]; //  4096 B

    const int tid  = threadIdx.x;
    const int w    = tid >> 5;          // 0..7
    const int lane = tid & 31;
    const int p    = w & 3;             // chain slot / pair id
    const int b    = blockIdx.x * 4 + p;

    // stage Bm as half2 (Bm[m][2l], Bm[m][2l+1])
    for (int i = tid; i < MM * 32; i += 256) {
        int m = i >> 5, l = i & 31;
        sBh[i] = h2u(__floats2half2_rn(Bm[m * SS + 2 * l], Bm[m * SS + 2 * l + 1]));
    }
    __syncthreads();

    if (w >= 4) {
        // ------------------ decoder warp for chain b ------------------
        const float4* xc = (const float4*)(x + (size_t)b * TT * MM);
        for (int c = 0; c < NCHUNK; c++) {
            unsigned char* dst = sObs[p][c & 1];
            const float4* base = xc + c * (CHUNK * MM / 4);   // 16000 float4/chunk
            const unsigned jbase = c * (CHUNK * MM);
            const unsigned rbase = c * CHUNK;
            for (int i = lane; i < CHUNK * MM / 4; i += 32) {
                float4 v = __ldcs(base + i);
                unsigned j = jbase + 4u * i;
                if (v.x > 0.5f) { unsigned r = j / 125u;        dst[r - rbase] = (unsigned char)(j - r * 125u); }
                if (v.y > 0.5f) { unsigned r = (j + 1) / 125u;  dst[r - rbase] = (unsigned char)(j + 1 - r * 125u); }
                if (v.z > 0.5f) { unsigned r = (j + 2) / 125u;  dst[r - rbase] = (unsigned char)(j + 2 - r * 125u); }
                if (v.w > 0.5f) { unsigned r = (j + 3) / 125u;  dst[r - rbase] = (unsigned char)(j + 3 - r * 125u); }
            }
            pair_bar(p);   // chunk c ready; scanner freed the other buffer by arriving
        }
    } else {
        // ------------------ scan warp for chain b ------------------
        // A-table in fp16 pairs: aT[k] = (A[k][2l], A[k][2l+1]) — 64 regs
        __half2 aT[64];
#pragma unroll
        for (int k = 0; k < 64; k++)
            aT[k] = __floats2half2_rn(A[k * SS + 2 * lane], A[k * SS + 2 * lane + 1]);
        const float i0 = Ivec[2 * lane];
        const float i1 = Ivec[2 * lane + 1];

        unsigned* buf0 = sAh[p][0];
        unsigned* buf1 = sAh[p][1];
        __half2 sdup = __float2half2_rn(1.0f);
        int exA = 0, esum = 0;
        float z = 1.0f;

        for (int c = 0; c < NCHUNK; c++) {
            pair_bar(p);
            const unsigned char* obs = sObs[p][c & 1];
            if (c == 0) {
                // first block: step 0 takes the INIT path
                uint2 ow = *(const uint2*)obs;
#pragma unroll
                for (int i = 0; i < 8; i++) {
                    unsigned word = (i < 4) ? ow.x : ow.y;
                    int ob = (word >> ((i & 3) * 8)) & 0xff;
                    if (i == 0)
                        hmm_step<true >(i, ob, sBh, buf0, buf1, buf0, buf1,
                                        aT, sdup, exA, esum, z, lane, i0, i1);
                    else
                        hmm_step<false>(i, ob, sBh, buf0, buf1, buf0, buf1,
                                        aT, sdup, exA, esum, z, lane, i0, i1);
                }
                for (int blk = 1; blk < CHUNK / 8; blk++) {
                    uint2 o2 = *(const uint2*)(obs + blk * 8);
#pragma unroll
                    for (int i = 0; i < 8; i++) {
                        unsigned word = (i < 4) ? o2.x : o2.y;
                        int ob = (word >> ((i & 3) * 8)) & 0xff;
                        hmm_step<false>(i, ob, sBh, buf0, buf1, buf0, buf1,
                                        aT, sdup, exA, esum, z, lane, i0, i1);
                    }
                }
            } else {
                for (int blk = 0; blk < CHUNK / 8; blk++) {
                    uint2 o2 = *(const uint2*)(obs + blk * 8);
#pragma unroll
                    for (int i = 0; i < 8; i++) {
                        unsigned word = (i < 4) ? o2.x : o2.y;
                        int ob = (word >> ((i & 3) * 8)) & 0xff;
                        hmm_step<false>(i, ob, sBh, buf0, buf1, buf0, buf1,
                                        aT, sdup, exA, esum, z, lane, i0, i1);
                    }
                }
            }
        }

        // ll = (sum of applied log2 scales)*ln2 + log(Z of final stored alpha)
        if (lane == 0) out[b] = (float)esum * 0.6931471805599453f + logf(z);
    }
}

extern "C" void kernel_launch(void* const* d_in, const int* in_sizes, int n_in,
                              void* d_out, int out_size) {
    const float* x  = (const float*)d_in[0];   // [512, 4096, 125]
    const float* I  = (const float*)d_in[1];   // [1, 64]
    const float* A  = (const float*)d_in[2];   // [64, 64]
    const float* Bm = (const float*)d_in[3];   // [125, 64]
    float* out = (float*)d_out;                // [512, 1]

    fused_hmm_kernel<<<BB / 4, 256>>>(x, I, A, Bm, out);
}

// round 17
// speedup vs baseline: 1.9489x; 1.0011x over previous
#include <cuda_runtime.h>
#include <cuda_fp16.h>
#include <cstdint>

#define BB 512
#define TT 4096
#define SS 64
#define MM 125
#define CHUNK 512                 // time-steps per producer/consumer chunk
#define NCHUNK (TT / CHUNK)       // 8

// pair rendezvous: scanner warp p and decoder warp p+4, named barrier p+1
__device__ __forceinline__ void pair_bar(int p) {
    asm volatile("bar.sync %0, 64;" :: "r"(p + 1) : "memory");
}

__device__ __forceinline__ __half2 u2h(unsigned v) { return *(__half2*)&v; }
__device__ __forceinline__ unsigned h2u(__half2 v) { return *(unsigned*)&v; }

// 2^-ex as a dup half2 (ex pre-clamped to [-14,14])
__device__ __forceinline__ __half2 pow2_dup(int ex) {
    unsigned hb = (unsigned)(15 - ex) << 10;     // fp16 exponent field
    return u2h(hb | (hb << 16));
}

// ---------------------------------------------------------------------------
// Fused kernel, 256 threads/CTA, 128 CTAs:
//   warps 0-3 : scan warps, one chain each. Alpha lives in REGISTERS
//               (1 half2/lane = states 2l, 2l+1); the all-to-all for the
//               matvec goes through the shuffle network, NOT the smem
//               crossbar (which profiling showed to be the binding resource).
//   warps 4-7 : decoder warps, stream + argmax-decode the partner chain.
// ---------------------------------------------------------------------------
__global__ void __launch_bounds__(256, 1) fused_hmm_kernel(
    const float* __restrict__ x,
    const float* __restrict__ Ivec,
    const float* __restrict__ A,
    const float* __restrict__ Bm,
    float* __restrict__ out)
{
    __shared__ __align__(16) unsigned sBh[MM * 32];              // 16000 B, half2 e-pairs
    __shared__ __align__(16) unsigned char sObs[4][2][CHUNK + 8];// obs bytes (+pad for lookahead)

    const int tid  = threadIdx.x;
    const int w    = tid >> 5;          // 0..7
    const int lane = tid & 31;
    const int p    = w & 3;             // chain slot / pair id
    const int b    = blockIdx.x * 4 + p;

    // stage Bm as half2 (Bm[m][2l], Bm[m][2l+1])
    for (int i = tid; i < MM * 32; i += 256) {
        int m = i >> 5, l = i & 31;
        sBh[i] = h2u(__floats2half2_rn(Bm[m * SS + 2 * l], Bm[m * SS + 2 * l + 1]));
    }
    __syncthreads();

    if (w >= 4) {
        // ------------------ decoder warp for chain b ------------------
        const float4* xc = (const float4*)(x + (size_t)b * TT * MM);
        for (int c = 0; c < NCHUNK; c++) {
            unsigned char* dst = sObs[p][c & 1];
            const float4* base = xc + c * (CHUNK * MM / 4);   // 16000 float4/chunk
            const unsigned jbase = c * (CHUNK * MM);
            const unsigned rbase = c * CHUNK;
            for (int i = lane; i < CHUNK * MM / 4; i += 32) {
                float4 v = __ldcs(base + i);
                unsigned j = jbase + 4u * i;
                if (v.x > 0.5f) { unsigned r = j / 125u;        dst[r - rbase] = (unsigned char)(j - r * 125u); }
                if (v.y > 0.5f) { unsigned r = (j + 1) / 125u;  dst[r - rbase] = (unsigned char)(j + 1 - r * 125u); }
                if (v.z > 0.5f) { unsigned r = (j + 2) / 125u;  dst[r - rbase] = (unsigned char)(j + 2 - r * 125u); }
                if (v.w > 0.5f) { unsigned r = (j + 3) / 125u;  dst[r - rbase] = (unsigned char)(j + 3 - r * 125u); }
            }
            pair_bar(p);   // chunk c ready; scanner freed the other buffer by arriving
        }
    } else {
        // ------------------ scan warp for chain b ------------------
        // A-tables (loop-invariant). Slot j pairs with the alpha pair owned by
        // source lane sigma = (lane + j) & 31, i.e. states 2*sigma, 2*sigma+1.
        //   aP[j] = (A[2s][2l],   A[2s+1][2l+1])
        //   aQ[j] = (A[2s][2l+1], A[2s+1][2l])
        // accP += pair * aP;  accQ += pair * aQ;
        // R = accP + halfswap(accQ)  ->  exact (R[2l], R[2l+1]).
        __half2 aP[32], aQ[32];
        const int s0 = 2 * lane, s1 = 2 * lane + 1;
#pragma unroll
        for (int j = 0; j < 32; j++) {
            int sg = (lane + j) & 31;
            aP[j] = __floats2half2_rn(A[(2 * sg) * SS + s0], A[(2 * sg + 1) * SS + s1]);
            aQ[j] = __floats2half2_rn(A[(2 * sg) * SS + s1], A[(2 * sg + 1) * SS + s0]);
        }
        const float i0 = Ivec[s0];
        const float i1 = Ivec[s1];

        unsigned alpha_u = 0;            // lane's alpha pair (half2 bits)
        __half2 sdup = __float2half2_rn(1.0f);
        int exA = 0, esum = 0;

        // ---- t = 0 (chunk 0) ----
        pair_bar(p);
        {
            int ob = sObs[p][0][0];
            __half2 e = u2h(sBh[ob * 32 + lane]);
            float u0 = __low2float(e)  * i0;        // fp32 init, then center
            float u1 = __high2float(e) * i1;
            // center lane 0's entry at 1 (uniform power-of-two; exact, logged)
            float w0 = __shfl_sync(0xffffffffu, u0, 0);
            int ex = (int)((__float_as_uint(w0) >> 23) & 0xff) - 127;
            esum = ex;
            float sc = __uint_as_float((unsigned)(127 - ex) << 23);   // 2^-ex
            __half2 u = __floats2half2_rn(u0 * sc, u1 * sc);
            alpha_u = h2u(u);
            // lag-1 renorm source for the next step
            float z0 = __shfl_sync(0xffffffffu, __low2float(u), 0);
            int ex2 = (int)((__float_as_uint(z0) >> 23) & 0xff) - 127;
            ex2 = ex2 < -14 ? -14 : (ex2 > 14 ? 14 : ex2);
            exA = ex2;
            sdup = pow2_dup(ex2);
        }

        for (int c = 0; c < NCHUNK; c++) {
            if (c) pair_bar(p);
            const unsigned char* obs = sObs[p][c & 1];
            const int t0 = (c == 0) ? 1 : 0;
#pragma unroll 4
            for (int tt = t0; tt < CHUNK; tt++) {
                int ob = obs[tt];
                __half2 e = u2h(sBh[ob * 32 + lane]);     // conflict-free LDS.32

                // matvec via rotation shuffles: alpha never touches smem
                unsigned av = alpha_u;
                __half2 P0 = __float2half2_rn(0.f), P1 = __float2half2_rn(0.f);
                __half2 Q0 = __float2half2_rn(0.f), Q1 = __float2half2_rn(0.f);
#pragma unroll
                for (int j = 0; j < 32; j += 2) {
                    unsigned g0 = __shfl_sync(0xffffffffu, av, (lane + j) & 31);
                    unsigned g1 = __shfl_sync(0xffffffffu, av, (lane + j + 1) & 31);
                    P0 = __hfma2(u2h(g0), aP[j],     P0);
                    Q0 = __hfma2(u2h(g0), aQ[j],     Q0);
                    P1 = __hfma2(u2h(g1), aP[j + 1], P1);
                    Q1 = __hfma2(u2h(g1), aQ[j + 1], Q1);
                }
                __half2 P = __hadd2(P0, P1);
                unsigned qv = h2u(__hadd2(Q0, Q1));
                qv = (qv >> 16) | (qv << 16);             // halfswap(accQ)
                __half2 R = __hadd2(P, u2h(qv));

                __half2 u = __hmul2(__hmul2(e, R), sdup); // apply lagged scale
                esum += exA;                              // account applied power
                alpha_u = h2u(u);

                // lag-1 renorm: center lane 0's entry at 1; consumed next step
                float z0 = __shfl_sync(0xffffffffu, __low2float(u), 0);
                int ex = (int)((__float_as_uint(z0) >> 23) & 0xff) - 127;
                ex = ex < -14 ? -14 : (ex > 14 ? 14 : ex);
                exA = ex;
                sdup = pow2_dup(ex);
            }
        }

        // final: exact Z over all 64 states (fp32 butterfly) + one log
        __half2 uf = u2h(alpha_u);
        float z = __low2float(uf) + __high2float(uf);
#pragma unroll
        for (int o = 16; o; o >>= 1) z += __shfl_xor_sync(0xffffffffu, z, o);
        if (lane == 0) out[b] = (float)esum * 0.6931471805599453f + logf(z);
    }
}

extern "C" void kernel_launch(void* const* d_in, const int* in_sizes, int n_in,
                              void* d_out, int out_size) {
    const float* x  = (const float*)d_in[0];   // [512, 4096, 125]
    const float* I  = (const float*)d_in[1];   // [1, 64]
    const float* A  = (const float*)d_in[2];   // [64, 64]
    const float* Bm = (const float*)d_in[3];   // [125, 64]
    float* out = (float*)d_out;                // [512, 1]

    fused_hmm_kernel<<<BB / 4, 256>>>(x, I, A, Bm, out);
}